// round 5
// baseline (speedup 1.0000x reference)
#include <cuda_runtime.h>
#include <math_constants.h>

#define H     128
#define T     16          // ops per tile (per block)
#define ROWP  20          // padded shared row stride (floats); 20*4=80B keeps 16B align, reduces conflicts
#define MAXM  1000
#define MAXJ  5000
#define MAXN  200000
#define RB    256         // reduction blocks
#define RT    256         // reduction threads

// ---- scratch (device globals; no allocation allowed) ----
__device__ float g_A[MAXM * H];       // x_m  @ W0[256:384]
__device__ float g_B[MAXJ * H];       // x_job@ W0[384:512]
__device__ float g_G[H];              // x_graph @ W0[0:256] + b0
__device__ float g_scores[MAXN];
__device__ float g_pmax[RB];
__device__ int   g_pidx[RB];
__device__ float g_ps1[RB];
__device__ float g_ps2[RB];
__device__ float g_gmax;
__device__ int   g_gidx;

// ============================================================================
// Precompute: per-row 128-wide matvecs against the three W0 slabs.
// grid = M + J + 1 blocks, 128 threads.  Thread k computes output feature k.
// ============================================================================
__global__ __launch_bounds__(H) void precompute_kernel(
    const float* __restrict__ xg, const float* __restrict__ xm,
    const float* __restrict__ xj, const float* __restrict__ W0,
    const float* __restrict__ b0, int M, int J)
{
    __shared__ float xs[2 * H];
    int r = blockIdx.x, k = threadIdx.x;
    if (r < M) {
        xs[k] = xm[r * H + k];
        __syncthreads();
        float acc = 0.f;
        const float* w = W0 + (2 * H) * H + k;
        #pragma unroll 8
        for (int i = 0; i < H; i++) acc = fmaf(xs[i], w[i * H], acc);
        g_A[r * H + k] = acc;
    } else if (r < M + J) {
        int rr = r - M;
        xs[k] = xj[rr * H + k];
        __syncthreads();
        float acc = 0.f;
        const float* w = W0 + (3 * H) * H + k;
        #pragma unroll 8
        for (int i = 0; i < H; i++) acc = fmaf(xs[i], w[i * H], acc);
        g_B[rr * H + k] = acc;
    } else {
        xs[k] = xg[k];
        xs[H + k] = xg[H + k];
        __syncthreads();
        float acc = b0[k];
        const float* w = W0 + k;
        #pragma unroll 8
        for (int i = 0; i < 2 * H; i++) acc = fmaf(xs[i], w[i * H], acc);
        g_G[k] = acc;
    }
}

// ============================================================================
// Score kernel: one block = T=16 ops. Gen phase builds H0 tile (128 feats x 16
// ops, feature-major, t-pairs contiguous for LDS.64 -> f32x2). Compute phase:
// thread k owns hidden unit k, packed fma.rn.f32x2 over 8 op-pairs, then
// relu + W2 dot, warp-shuffle + cross-warp reduce to 16 scores.
// ============================================================================
__global__ __launch_bounds__(H) void score_kernel(
    const int* __restrict__ m_ids, const int* __restrict__ j_ids,
    const float* __restrict__ W1, const float* __restrict__ b1,
    const float* __restrict__ W2, const float* __restrict__ b2p, int N)
{
    __shared__ __align__(16) float H0s[H * ROWP];
    __shared__ int ids[2 * T];
    __shared__ float red[4][T];

    int tid = threadIdx.x;               // 0..127
    int base = blockIdx.x * T;
    int cnt = N - base; if (cnt > T) cnt = T;

    if (tid < T) {
        int t = tid;
        ids[t]     = (t < cnt) ? m_ids[base + t] : 0;
        ids[T + t] = (t < cnt) ? j_ids[base + t] : 0;
    }
    __syncthreads();

    // ---- gen phase: thread tid = feature index i ----
    float gi = g_G[tid];
    #pragma unroll
    for (int t = 0; t < T; t++) {
        float u = gi + g_A[ids[t] * H + tid] + g_B[ids[T + t] * H + tid];
        H0s[tid * ROWP + t] = fmaxf(u, 0.f);
    }
    __syncthreads();

    // ---- compute phase: thread tid = hidden unit k ----
    unsigned long long acc[8];
    #pragma unroll
    for (int p = 0; p < 8; p++) acc[p] = 0ull;

    const float* w1p = W1 + tid;         // W1[i*H + k]
    #pragma unroll 4
    for (int i = 0; i < H; i++) {
        float w = __ldg(w1p + i * H);
        unsigned long long wp;
        asm("mov.b64 %0, {%1, %1};" : "=l"(wp) : "f"(w));
        const unsigned long long* hp =
            (const unsigned long long*)(H0s + i * ROWP);  // 8B-aligned pairs
        #pragma unroll
        for (int p = 0; p < 8; p++) {
            unsigned long long hv = hp[p];                 // broadcast LDS.64
            asm("fma.rn.f32x2 %0, %1, %2, %0;" : "+l"(acc[p]) : "l"(hv), "l"(wp));
        }
    }

    float b1k = b1[tid];
    float w2k = W2[tid];
    float c[T];
    #pragma unroll
    for (int p = 0; p < 8; p++) {
        float lo, hi;
        asm("mov.b64 {%0, %1}, %2;" : "=f"(lo), "=f"(hi) : "l"(acc[p]));
        c[2 * p]     = fmaxf(lo + b1k, 0.f) * w2k;
        c[2 * p + 1] = fmaxf(hi + b1k, 0.f) * w2k;
    }

    int lane = tid & 31, wid = tid >> 5;
    #pragma unroll
    for (int t = 0; t < T; t++) {
        float v = c[t];
        v += __shfl_xor_sync(0xffffffffu, v, 16);
        v += __shfl_xor_sync(0xffffffffu, v, 8);
        v += __shfl_xor_sync(0xffffffffu, v, 4);
        v += __shfl_xor_sync(0xffffffffu, v, 2);
        v += __shfl_xor_sync(0xffffffffu, v, 1);
        if (lane == 0) red[wid][t] = v;
    }
    __syncthreads();

    if (tid < cnt) {
        float s = red[0][tid] + red[1][tid] + red[2][tid] + red[3][tid] + b2p[0];
        g_scores[base + tid] = s;
    }
}

// ============================================================================
// Deterministic two-stage reductions (fixed tree order, first-index tie-break).
// ============================================================================
__global__ __launch_bounds__(RT) void reduce_max_kernel(int N)
{
    __shared__ float sv[RT];
    __shared__ int   si[RT];
    int tid = threadIdx.x;
    float best = -CUDART_INF_F;
    int bi = 0x7fffffff;
    for (int i = blockIdx.x * RT + tid; i < N; i += RB * RT) {
        float v = g_scores[i];
        if (v > best) { best = v; bi = i; }   // ascending i -> keeps first max
    }
    sv[tid] = best; si[tid] = bi;
    __syncthreads();
    for (int off = RT >> 1; off; off >>= 1) {
        if (tid < off) {
            float v = sv[tid + off]; int j = si[tid + off];
            if (v > sv[tid] || (v == sv[tid] && j < si[tid])) { sv[tid] = v; si[tid] = j; }
        }
        __syncthreads();
    }
    if (tid == 0) { g_pmax[blockIdx.x] = sv[0]; g_pidx[blockIdx.x] = si[0]; }
}

__global__ __launch_bounds__(RB) void final_max_kernel()
{
    __shared__ float sv[RB];
    __shared__ int   si[RB];
    int tid = threadIdx.x;
    sv[tid] = g_pmax[tid]; si[tid] = g_pidx[tid];
    __syncthreads();
    for (int off = RB >> 1; off; off >>= 1) {
        if (tid < off) {
            float v = sv[tid + off]; int j = si[tid + off];
            if (v > sv[tid] || (v == sv[tid] && j < si[tid])) { sv[tid] = v; si[tid] = j; }
        }
        __syncthreads();
    }
    if (tid == 0) { g_gmax = sv[0]; g_gidx = si[0]; }
}

__global__ __launch_bounds__(RT) void reduce_sum_kernel(int N)
{
    __shared__ float s1s[RT], s2s[RT];
    int tid = threadIdx.x;
    float m = g_gmax;
    float s1 = 0.f, s2 = 0.f;
    for (int i = blockIdx.x * RT + tid; i < N; i += RB * RT) {
        float d = g_scores[i] - m;
        float e = expf(d);
        s1 += e;
        s2 += e * d;
    }
    s1s[tid] = s1; s2s[tid] = s2;
    __syncthreads();
    for (int off = RT >> 1; off; off >>= 1) {
        if (tid < off) { s1s[tid] += s1s[tid + off]; s2s[tid] += s2s[tid + off]; }
        __syncthreads();
    }
    if (tid == 0) { g_ps1[blockIdx.x] = s1s[0]; g_ps2[blockIdx.x] = s2s[0]; }
}

__global__ __launch_bounds__(RB) void finalize_kernel(float* __restrict__ out, int out_size)
{
    __shared__ float s1s[RB], s2s[RB];
    int tid = threadIdx.x;
    s1s[tid] = g_ps1[tid]; s2s[tid] = g_ps2[tid];
    __syncthreads();
    for (int off = RB >> 1; off; off >>= 1) {
        if (tid < off) { s1s[tid] += s1s[tid + off]; s2s[tid] += s2s[tid + off]; }
        __syncthreads();
    }
    if (tid == 0) {
        float S1 = s1s[0], S2 = s2s[0];
        float lz = logf(S1);
        // idx is the argmax => its shifted score d=0:
        //   probs[idx] = 1/S1, logp[idx] = -log S1, entropy = log S1 - S2/S1
        float vals[4];
        vals[0] = (float)g_gidx;
        vals[1] = 1.f / S1;
        vals[2] = -lz;
        vals[3] = lz - S2 / S1;
        int nw = out_size < 4 ? out_size : 4;
        for (int i = 0; i < nw; i++) out[i] = vals[i];
    }
}

// ============================================================================
extern "C" void kernel_launch(void* const* d_in, const int* in_sizes, int n_in,
                              void* d_out, int out_size)
{
    const float* xg  = (const float*)d_in[0];   // (1, 2H)
    const float* xm  = (const float*)d_in[1];   // (M, H)
    const float* xj  = (const float*)d_in[2];   // (J, H)
    const int*   mi  = (const int*)  d_in[3];   // (N,)
    const int*   ji  = (const int*)  d_in[4];   // (N,)
    const float* W0  = (const float*)d_in[5];   // (4H, H)
    const float* b0  = (const float*)d_in[6];   // (H,)
    const float* W1  = (const float*)d_in[7];   // (H, H)
    const float* b1  = (const float*)d_in[8];   // (H,)
    const float* W2  = (const float*)d_in[9];   // (H, 1)
    const float* b2  = (const float*)d_in[10];  // (1,)

    int N = in_sizes[3];
    int M = in_sizes[1] / H;
    int J = in_sizes[2] / H;
    float* out = (float*)d_out;

    precompute_kernel<<<M + J + 1, H>>>(xg, xm, xj, W0, b0, M, J);
    score_kernel<<<(N + T - 1) / T, H>>>(mi, ji, W1, b1, W2, b2, N);
    reduce_max_kernel<<<RB, RT>>>(N);
    final_max_kernel<<<1, RB>>>();
    reduce_sum_kernel<<<RB, RT>>>(N);
    finalize_kernel<<<1, RB>>>(out, out_size);
}

// round 6
// speedup vs baseline: 1.0287x; 1.0287x over previous
#include <cuda_runtime.h>
#include <math_constants.h>

#define H     128
#define T     32          // ops per tile (per block)
#define ROWP  36          // padded shared row stride (floats); 144B = 16B-aligned, STS.128 conflict-free
#define MAXM  1000
#define MAXJ  5000
#define MAXN  200000
#define RB    256         // reduction blocks
#define RT    256         // reduction threads

// ---- scratch (device globals; no allocation allowed) ----
__device__ float g_A[MAXM * H];       // x_m  @ W0[256:384]
__device__ float g_B[MAXJ * H];       // x_job@ W0[384:512]
__device__ float g_G[H];              // x_graph @ W0[0:256] + b0
__device__ float g_scores[MAXN];
__device__ unsigned long long g_amax; // packed (ordered(score) << 32) | ~idx
__device__ float g_ps1[RB];
__device__ float g_ps2[RB];

// ============================================================================
// Precompute: per-row 128-wide matvecs against the three W0 slabs.
// grid = M + J + 1 blocks, 128 threads.  Thread k computes output feature k.
// Last block also resets the global argmax key.
// ============================================================================
__global__ __launch_bounds__(H) void precompute_kernel(
    const float* __restrict__ xg, const float* __restrict__ xm,
    const float* __restrict__ xj, const float* __restrict__ W0,
    const float* __restrict__ b0, int M, int J)
{
    __shared__ float xs[2 * H];
    int r = blockIdx.x, k = threadIdx.x;
    if (r < M) {
        xs[k] = xm[r * H + k];
        __syncthreads();
        float acc = 0.f;
        const float* w = W0 + (2 * H) * H + k;
        #pragma unroll 8
        for (int i = 0; i < H; i++) acc = fmaf(xs[i], w[i * H], acc);
        g_A[r * H + k] = acc;
    } else if (r < M + J) {
        int rr = r - M;
        xs[k] = xj[rr * H + k];
        __syncthreads();
        float acc = 0.f;
        const float* w = W0 + (3 * H) * H + k;
        #pragma unroll 8
        for (int i = 0; i < H; i++) acc = fmaf(xs[i], w[i * H], acc);
        g_B[rr * H + k] = acc;
    } else {
        if (k == 0) g_amax = 0ull;
        xs[k] = xg[k];
        xs[H + k] = xg[H + k];
        __syncthreads();
        float acc = b0[k];
        const float* w = W0 + k;
        #pragma unroll 8
        for (int i = 0; i < 2 * H; i++) acc = fmaf(xs[i], w[i * H], acc);
        g_G[k] = acc;
    }
}

// ============================================================================
// Score kernel: one block = T=32 ops. Gen phase builds H0 tile (128 feats x
// 32 ops, feature-major, STS.128 groups of 4 ops). Compute phase: thread k
// owns hidden unit k, 8 broadcast LDS.128 + 16 packed fma.rn.f32x2 per i.
// Epilogue: relu + W2 scale, 31-shuffle multi-value butterfly (lane l ends
// with op t=l), cross-warp add, score store + fused deterministic argmax via
// packed-key atomicMax.
// ============================================================================
__global__ __launch_bounds__(H) void score_kernel(
    const int* __restrict__ m_ids, const int* __restrict__ j_ids,
    const float* __restrict__ W1, const float* __restrict__ b1,
    const float* __restrict__ W2, const float* __restrict__ b2p, int N)
{
    __shared__ __align__(16) float H0s[H * ROWP];
    __shared__ int ids[2 * T];
    __shared__ float red[4][T];

    int tid = threadIdx.x;               // 0..127
    int base = blockIdx.x * T;
    int cnt = N - base; if (cnt > T) cnt = T;

    if (tid < 2 * T) {
        int t = tid & (T - 1);
        if (tid < T) ids[tid] = (t < cnt) ? m_ids[base + t] : 0;
        else         ids[tid] = (t < cnt) ? j_ids[base + t] : 0;
    }
    __syncthreads();

    // ---- gen phase: thread tid = feature index i; 4 ops per STS.128 ----
    {
        float gi = g_G[tid];
        const float* Arow = g_A + tid;
        const float* Brow = g_B + tid;
        #pragma unroll
        for (int g = 0; g < T / 4; g++) {
            float4 u;
            u.x = fmaxf(gi + Arow[ids[4*g+0] * H] + Brow[ids[T + 4*g+0] * H], 0.f);
            u.y = fmaxf(gi + Arow[ids[4*g+1] * H] + Brow[ids[T + 4*g+1] * H], 0.f);
            u.z = fmaxf(gi + Arow[ids[4*g+2] * H] + Brow[ids[T + 4*g+2] * H], 0.f);
            u.w = fmaxf(gi + Arow[ids[4*g+3] * H] + Brow[ids[T + 4*g+3] * H], 0.f);
            *(float4*)(H0s + tid * ROWP + 4 * g) = u;   // conflict-free STS.128
        }
    }
    __syncthreads();

    // ---- compute phase: thread tid = hidden unit k ----
    unsigned long long acc[T / 2];
    #pragma unroll
    for (int p = 0; p < T / 2; p++) acc[p] = 0ull;

    const float* w1p = W1 + tid;             // W1[i*H + k]
    const float* hrow = H0s;
    #pragma unroll 1
    for (int i = 0; i < H; i++) {
        float w = __ldg(w1p); w1p += H;
        unsigned long long wp;
        asm("mov.b64 %0, {%1, %1};" : "=l"(wp) : "f"(w));
        #pragma unroll
        for (int p = 0; p < 8; p++) {
            ulonglong2 hv = *(const ulonglong2*)(hrow + 4 * p);  // broadcast LDS.128
            asm("fma.rn.f32x2 %0, %1, %2, %0;" : "+l"(acc[2*p])   : "l"(hv.x), "l"(wp));
            asm("fma.rn.f32x2 %0, %1, %2, %0;" : "+l"(acc[2*p+1]) : "l"(hv.y), "l"(wp));
        }
        hrow += ROWP;
    }

    // ---- epilogue ----
    float b1k = b1[tid];
    float w2k = W2[tid];
    float v[T];
    #pragma unroll
    for (int p = 0; p < T / 2; p++) {
        float lo, hi;
        asm("mov.b64 {%0, %1}, %2;" : "=f"(lo), "=f"(hi) : "l"(acc[p]));
        v[2*p]   = fmaxf(lo + b1k, 0.f) * w2k;
        v[2*p+1] = fmaxf(hi + b1k, 0.f) * w2k;
    }

    int lane = tid & 31, wid = tid >> 5;
    // multi-value butterfly: after 5 stages lane l holds sum over 32 lanes
    // of op t=l (31 shuffles total).
    int slots = T;
    #pragma unroll
    for (int off = 16; off >= 1; off >>= 1) {
        int half = slots >> 1;
        bool up = (lane & off) != 0;
        #pragma unroll
        for (int j = 0; j < 16; j++) {
            if (j < half) {
                float send = up ? v[j] : v[j + half];
                float keep = up ? v[j + half] : v[j];
                float recv = __shfl_xor_sync(0xffffffffu, send, off);
                v[j] = keep + recv;
            }
        }
        slots = half;
    }
    red[wid][lane] = v[0];
    __syncthreads();

    if (wid == 0) {
        int t = lane;
        unsigned long long key = 0ull;
        if (t < cnt) {
            float s = red[0][t] + red[1][t] + red[2][t] + red[3][t] + b2p[0];
            g_scores[base + t] = s;
            unsigned fu = __float_as_uint(s);
            unsigned ord = (fu & 0x80000000u) ? ~fu : (fu | 0x80000000u);
            key = ((unsigned long long)ord << 32) | (unsigned)(~(unsigned)(base + t));
        }
        #pragma unroll
        for (int off = 16; off >= 1; off >>= 1) {
            unsigned long long o = __shfl_xor_sync(0xffffffffu, key, off);
            if (o > key) key = o;
        }
        if (lane == 0) atomicMax(&g_amax, key);
    }
}

// ============================================================================
// Deterministic two-stage sum reduction (fixed tree order).
// ============================================================================
__device__ __forceinline__ float decode_max(unsigned long long key) {
    unsigned ord = (unsigned)(key >> 32);
    unsigned fu = (ord & 0x80000000u) ? (ord ^ 0x80000000u) : ~ord;
    return __uint_as_float(fu);
}

__global__ __launch_bounds__(RT) void reduce_sum_kernel(int N)
{
    __shared__ float s1s[RT], s2s[RT];
    int tid = threadIdx.x;
    float m = decode_max(g_amax);
    float s1 = 0.f, s2 = 0.f;
    for (int i = blockIdx.x * RT + tid; i < N; i += RB * RT) {
        float d = g_scores[i] - m;
        float e = expf(d);
        s1 += e;
        s2 += e * d;
    }
    s1s[tid] = s1; s2s[tid] = s2;
    __syncthreads();
    for (int off = RT >> 1; off; off >>= 1) {
        if (tid < off) { s1s[tid] += s1s[tid + off]; s2s[tid] += s2s[tid + off]; }
        __syncthreads();
    }
    if (tid == 0) { g_ps1[blockIdx.x] = s1s[0]; g_ps2[blockIdx.x] = s2s[0]; }
}

__global__ __launch_bounds__(RB) void finalize_kernel(float* __restrict__ out, int out_size)
{
    __shared__ float s1s[RB], s2s[RB];
    int tid = threadIdx.x;
    s1s[tid] = g_ps1[tid]; s2s[tid] = g_ps2[tid];
    __syncthreads();
    for (int off = RB >> 1; off; off >>= 1) {
        if (tid < off) { s1s[tid] += s1s[tid + off]; s2s[tid] += s2s[tid + off]; }
        __syncthreads();
    }
    if (tid == 0) {
        unsigned long long key = g_amax;
        int idx = (int)(~(unsigned)key);
        float S1 = s1s[0], S2 = s2s[0];
        float lz = logf(S1);
        // idx is the argmax => its shifted score d=0:
        //   probs[idx] = 1/S1, logp[idx] = -log S1, entropy = log S1 - S2/S1
        float vals[4];
        vals[0] = (float)idx;
        vals[1] = 1.f / S1;
        vals[2] = -lz;
        vals[3] = lz - S2 / S1;
        int nw = out_size < 4 ? out_size : 4;
        for (int i = 0; i < nw; i++) out[i] = vals[i];
    }
}

// ============================================================================
extern "C" void kernel_launch(void* const* d_in, const int* in_sizes, int n_in,
                              void* d_out, int out_size)
{
    const float* xg  = (const float*)d_in[0];   // (1, 2H)
    const float* xm  = (const float*)d_in[1];   // (M, H)
    const float* xj  = (const float*)d_in[2];   // (J, H)
    const int*   mi  = (const int*)  d_in[3];   // (N,)
    const int*   ji  = (const int*)  d_in[4];   // (N,)
    const float* W0  = (const float*)d_in[5];   // (4H, H)
    const float* b0  = (const float*)d_in[6];   // (H,)
    const float* W1  = (const float*)d_in[7];   // (H, H)
    const float* b1  = (const float*)d_in[8];   // (H,)
    const float* W2  = (const float*)d_in[9];   // (H, 1)
    const float* b2  = (const float*)d_in[10];  // (1,)

    int N = in_sizes[3];
    int M = in_sizes[1] / H;
    int J = in_sizes[2] / H;
    float* out = (float*)d_out;

    precompute_kernel<<<M + J + 1, H>>>(xg, xm, xj, W0, b0, M, J);
    score_kernel<<<(N + T - 1) / T, H>>>(mi, ji, W1, b1, W2, b2, N);
    reduce_sum_kernel<<<RB, RT>>>(N);
    finalize_kernel<<<1, RB>>>(out, out_size);
}

// round 7
// speedup vs baseline: 1.1035x; 1.0727x over previous
#include <cuda_runtime.h>
#include <cuda_fp16.h>
#include <math_constants.h>

#define H     128
#define TOPS  64          // ops per score block
#define APAD  136         // halfs per A-smem row (272B: conflict-free frag LDS)
#define PR    16          // rows per precompute block
#define MAXM  1000
#define MAXJ  5000
#define MAXN  200000
#define RB    256
#define RT    256

// ---- scratch (device globals; no allocation allowed) ----
__device__ float  g_A[MAXM * H];       // x_m  @ W0[256:384]
__device__ float  g_B[MAXJ * H];       // x_job@ W0[384:512]
__device__ float  g_G[H];              // x_graph @ W0[0:256] + b0
__device__ __half g_W1h[H * H];        // W1 transposed [n][k], fp16 hi
__device__ __half g_W1l[H * H];        // fp16 lo residual
__device__ float  g_scores[MAXN];
__device__ unsigned long long g_amax;  // packed (ordered(score)<<32) | ~idx
__device__ float  g_ps1[RB], g_ps2[RB];

// ============================================================================
// Precompute. Block roles:
//   [0, nMB)            : 16 M-rows each,  W0 slab [2H:3H)
//   [nMB, nMB+nJB)      : 16 J-rows each,  W0 slab [3H:4H)
//   nMB+nJB             : G row (2H-wide matvec) + reset argmax
//   (nMB+nJB, +32]      : W1 -> transposed fp16 hi/lo split
// Each row-block keeps the W0 column value in a register and FMAs into 16
// row accumulators -> W0 L2 traffic divided by 16 vs one-row-per-block.
// ============================================================================
__global__ __launch_bounds__(H) void precompute_kernel(
    const float* __restrict__ xg, const float* __restrict__ xm,
    const float* __restrict__ xj, const float* __restrict__ W0,
    const float* __restrict__ b0, const float* __restrict__ W1,
    int M, int J, int nMB, int nJB)
{
    __shared__ __align__(16) float xsT[H * 20];   // [i][r], stride 20 floats
    int b = blockIdx.x, k = threadIdx.x;

    if (b < nMB + nJB) {
        bool isM = (b < nMB);
        int r0 = (isM ? b : b - nMB) * PR;
        int R  = isM ? M : J;
        const float* src = isM ? xm : xj;
        const float* w   = W0 + (isM ? 2 * H * H : 3 * H * H) + k;
        float* dst = isM ? g_A : g_B;
        int rows = R - r0; if (rows > PR) rows = PR;

        #pragma unroll
        for (int r = 0; r < PR; r++) {
            int rr = r0 + ((r < rows) ? r : 0);
            xsT[k * 20 + r] = src[rr * H + k];
        }
        __syncthreads();

        float acc[PR];
        #pragma unroll
        for (int r = 0; r < PR; r++) acc[r] = 0.f;

        #pragma unroll 2
        for (int i = 0; i < H; i++) {
            float wv = __ldg(w + i * H);
            const float4* xp = (const float4*)(xsT + i * 20);
            float4 x0 = xp[0], x1 = xp[1], x2 = xp[2], x3 = xp[3];
            acc[0]  = fmaf(x0.x, wv, acc[0]);  acc[1]  = fmaf(x0.y, wv, acc[1]);
            acc[2]  = fmaf(x0.z, wv, acc[2]);  acc[3]  = fmaf(x0.w, wv, acc[3]);
            acc[4]  = fmaf(x1.x, wv, acc[4]);  acc[5]  = fmaf(x1.y, wv, acc[5]);
            acc[6]  = fmaf(x1.z, wv, acc[6]);  acc[7]  = fmaf(x1.w, wv, acc[7]);
            acc[8]  = fmaf(x2.x, wv, acc[8]);  acc[9]  = fmaf(x2.y, wv, acc[9]);
            acc[10] = fmaf(x2.z, wv, acc[10]); acc[11] = fmaf(x2.w, wv, acc[11]);
            acc[12] = fmaf(x3.x, wv, acc[12]); acc[13] = fmaf(x3.y, wv, acc[13]);
            acc[14] = fmaf(x3.z, wv, acc[14]); acc[15] = fmaf(x3.w, wv, acc[15]);
        }
        for (int r = 0; r < rows; r++) dst[(r0 + r) * H + k] = acc[r];
    } else if (b == nMB + nJB) {
        if (k == 0) g_amax = 0ull;
        xsT[k] = xg[k];
        xsT[H + k] = xg[H + k];
        __syncthreads();
        float acc = b0[k];
        const float* w = W0 + k;
        #pragma unroll 8
        for (int i = 0; i < 2 * H; i++) acc = fmaf(xsT[i], w[i * H], acc);
        g_G[k] = acc;
    } else {
        // W1 -> [n][k] fp16 hi/lo. 32 blocks x 128 threads x 4 elems = 16384.
        int blkw = b - (nMB + nJB + 1);
        #pragma unroll
        for (int it = 0; it < 4; it++) {
            int e = blkw * 512 + it * H + k;      // coalesced read of W1[e]
            float wv = __ldg(W1 + e);
            __half hi = __float2half_rn(wv);
            __half lo = __float2half_rn(wv - __half2float(hi));
            int i = e >> 7, n = e & (H - 1);
            g_W1h[n * H + i] = hi;
            g_W1l[n * H + i] = lo;
        }
    }
}

// ============================================================================
// Score kernel: block = 64 ops, 256 threads (8 warps).
// Gen: gather H0 rows (fp32), relu, split to fp16 hi/lo tiles in smem.
// Compute: warp w = (mtile = w&3, nhalf = w>>2): C[16 x 64] via
//   mma.sync.m16n8k16 x 3 (hh + hl + lh split-fp16 = fp32-grade precision),
//   A frags from smem (LDS.32, conflict-free), B frags from global (L1-hot,
//   W1 hi/lo is 64KB total and persists in L1 across CTAs within the launch).
// Epilogue: +b1, relu, *W2, quad-shuffle row sums, cross-nhalf combine in
// smem, score store + deterministic packed-key atomicMax argmax.
// ============================================================================
__device__ __forceinline__ void mma_f16(float c[4], const unsigned a[4],
                                        const unsigned b[2])
{
    asm volatile(
        "mma.sync.aligned.m16n8k16.row.col.f32.f16.f16.f32 "
        "{%0,%1,%2,%3}, {%4,%5,%6,%7}, {%8,%9}, {%0,%1,%2,%3};"
        : "+f"(c[0]), "+f"(c[1]), "+f"(c[2]), "+f"(c[3])
        : "r"(a[0]), "r"(a[1]), "r"(a[2]), "r"(a[3]), "r"(b[0]), "r"(b[1]));
}

__global__ __launch_bounds__(256) void score_kernel(
    const int* __restrict__ m_ids, const int* __restrict__ j_ids,
    const float* __restrict__ b1, const float* __restrict__ W2,
    const float* __restrict__ b2p, int N)
{
    __shared__ __align__(16) __half Ah[TOPS * APAD];
    __shared__ __align__(16) __half Al[TOPS * APAD];
    __shared__ int   ids[2 * TOPS];
    __shared__ float b1s[H], w2s[H];
    __shared__ float red[2][TOPS];

    int tid = threadIdx.x;
    int base = blockIdx.x * TOPS;
    int cnt = N - base; if (cnt > TOPS) cnt = TOPS;

    if (tid < H) { b1s[tid] = b1[tid]; w2s[tid] = W2[tid]; }
    if (tid < TOPS)          ids[tid] = (tid < cnt) ? m_ids[base + tid] : 0;
    else if (tid < 2 * TOPS) {
        int t = tid - TOPS;
        ids[TOPS + t] = (t < cnt) ? j_ids[base + t] : 0;
    }
    __syncthreads();

    // ---- gen phase: 64 ops x 64 feat-pairs, coalesced float2 gathers ----
    #pragma unroll 4
    for (int it = 0; it < 16; it++) {
        int idx = it * 256 + tid;
        int op = idx >> 6, fp = idx & 63;
        int m = ids[op], j = ids[TOPS + op];
        float2 gv = *(const float2*)(g_G + fp * 2);
        float2 av = *(const float2*)(g_A + m * H + fp * 2);
        float2 bv = *(const float2*)(g_B + j * H + fp * 2);
        float x0 = fmaxf(gv.x + av.x + bv.x, 0.f);
        float x1 = fmaxf(gv.y + av.y + bv.y, 0.f);
        __half h0 = __float2half_rn(x0), h1 = __float2half_rn(x1);
        __half l0 = __float2half_rn(x0 - __half2float(h0));
        __half l1 = __float2half_rn(x1 - __half2float(h1));
        *(__half2*)(Ah + op * APAD + fp * 2) = __halves2half2(h0, h1);
        *(__half2*)(Al + op * APAD + fp * 2) = __halves2half2(l0, l1);
    }
    __syncthreads();

    // ---- mma phase ----
    int wlin = tid >> 5, lane = tid & 31;
    int mt = wlin & 3, nh = wlin >> 2;
    int g = lane >> 2, t = lane & 3;
    int m0 = mt * 16;

    float c[8][4];
    #pragma unroll
    for (int nt = 0; nt < 8; nt++)
        { c[nt][0] = c[nt][1] = c[nt][2] = c[nt][3] = 0.f; }

    const __half* ArG  = Ah + (m0 + g) * APAD;
    const __half* ArG8 = Ah + (m0 + g + 8) * APAD;
    const __half* AlG  = Al + (m0 + g) * APAD;
    const __half* AlG8 = Al + (m0 + g + 8) * APAD;
    const __half* Bh0  = g_W1h + (nh * 64 + g) * H + 2 * t;
    const __half* Bl0  = g_W1l + (nh * 64 + g) * H + 2 * t;

    #pragma unroll 2
    for (int ks = 0; ks < 8; ks++) {
        int kc = ks * 16 + 2 * t;
        unsigned ah[4], al[4];
        ah[0] = *(const unsigned*)(ArG  + kc);
        ah[1] = *(const unsigned*)(ArG8 + kc);
        ah[2] = *(const unsigned*)(ArG  + kc + 8);
        ah[3] = *(const unsigned*)(ArG8 + kc + 8);
        al[0] = *(const unsigned*)(AlG  + kc);
        al[1] = *(const unsigned*)(AlG8 + kc);
        al[2] = *(const unsigned*)(AlG  + kc + 8);
        al[3] = *(const unsigned*)(AlG8 + kc + 8);
        #pragma unroll
        for (int nt = 0; nt < 8; nt++) {
            unsigned bh[2], bl[2];
            const __half* bph = Bh0 + nt * 8 * H + ks * 16;
            const __half* bpl = Bl0 + nt * 8 * H + ks * 16;
            bh[0] = __ldg((const unsigned*)(bph));
            bh[1] = __ldg((const unsigned*)(bph + 8));
            bl[0] = __ldg((const unsigned*)(bpl));
            bl[1] = __ldg((const unsigned*)(bpl + 8));
            mma_f16(c[nt], ah, bh);   // hi*hi
            mma_f16(c[nt], ah, bl);   // hi*lo
            mma_f16(c[nt], al, bh);   // lo*hi
        }
    }

    // ---- epilogue: relu(+b1) * W2, row sums ----
    float sl = 0.f, sh = 0.f;
    #pragma unroll
    for (int nt = 0; nt < 8; nt++) {
        int n0 = nh * 64 + nt * 8 + 2 * t;
        float w20 = w2s[n0], w21 = w2s[n0 + 1];
        float bb0 = b1s[n0], bb1 = b1s[n0 + 1];
        sl += fmaxf(c[nt][0] + bb0, 0.f) * w20 + fmaxf(c[nt][1] + bb1, 0.f) * w21;
        sh += fmaxf(c[nt][2] + bb0, 0.f) * w20 + fmaxf(c[nt][3] + bb1, 0.f) * w21;
    }
    sl += __shfl_xor_sync(0xffffffffu, sl, 1);
    sl += __shfl_xor_sync(0xffffffffu, sl, 2);
    sh += __shfl_xor_sync(0xffffffffu, sh, 1);
    sh += __shfl_xor_sync(0xffffffffu, sh, 2);
    if (t == 0) {
        red[nh][m0 + g]     = sl;
        red[nh][m0 + g + 8] = sh;
    }
    __syncthreads();

    if (tid < TOPS) {
        unsigned long long key = 0ull;
        if (tid < cnt) {
            float s = red[0][tid] + red[1][tid] + b2p[0];
            g_scores[base + tid] = s;
            unsigned fu = __float_as_uint(s);
            unsigned ord = (fu & 0x80000000u) ? ~fu : (fu | 0x80000000u);
            key = ((unsigned long long)ord << 32) |
                  (unsigned)(~(unsigned)(base + tid));
        }
        #pragma unroll
        for (int off = 16; off >= 1; off >>= 1) {
            unsigned long long o = __shfl_xor_sync(0xffffffffu, key, off);
            if (o > key) key = o;
        }
        if ((tid & 31) == 0) atomicMax(&g_amax, key);
    }
}

// ============================================================================
// Deterministic two-stage sum reduction (fixed tree order).
// ============================================================================
__device__ __forceinline__ float decode_max(unsigned long long key) {
    unsigned ord = (unsigned)(key >> 32);
    unsigned fu = (ord & 0x80000000u) ? (ord ^ 0x80000000u) : ~ord;
    return __uint_as_float(fu);
}

__global__ __launch_bounds__(RT) void reduce_sum_kernel(int N)
{
    __shared__ float s1s[RT], s2s[RT];
    int tid = threadIdx.x;
    float m = decode_max(g_amax);
    float s1 = 0.f, s2 = 0.f;
    for (int i = blockIdx.x * RT + tid; i < N; i += RB * RT) {
        float d = g_scores[i] - m;
        float e = expf(d);
        s1 += e;
        s2 += e * d;
    }
    s1s[tid] = s1; s2s[tid] = s2;
    __syncthreads();
    for (int off = RT >> 1; off; off >>= 1) {
        if (tid < off) { s1s[tid] += s1s[tid + off]; s2s[tid] += s2s[tid + off]; }
        __syncthreads();
    }
    if (tid == 0) { g_ps1[blockIdx.x] = s1s[0]; g_ps2[blockIdx.x] = s2s[0]; }
}

__global__ __launch_bounds__(RB) void finalize_kernel(float* __restrict__ out, int out_size)
{
    __shared__ float s1s[RB], s2s[RB];
    int tid = threadIdx.x;
    s1s[tid] = g_ps1[tid]; s2s[tid] = g_ps2[tid];
    __syncthreads();
    for (int off = RB >> 1; off; off >>= 1) {
        if (tid < off) { s1s[tid] += s1s[tid + off]; s2s[tid] += s2s[tid + off]; }
        __syncthreads();
    }
    if (tid == 0) {
        unsigned long long key = g_amax;
        int idx = (int)(~(unsigned)key);
        float S1 = s1s[0], S2 = s2s[0];
        float lz = logf(S1);
        float vals[4];
        vals[0] = (float)idx;
        vals[1] = 1.f / S1;      // probs[idx]  (argmax => shifted score 0)
        vals[2] = -lz;           // logp[idx]
        vals[3] = lz - S2 / S1;  // entropy
        int nw = out_size < 4 ? out_size : 4;
        for (int i = 0; i < nw; i++) out[i] = vals[i];
    }
}

// ============================================================================
extern "C" void kernel_launch(void* const* d_in, const int* in_sizes, int n_in,
                              void* d_out, int out_size)
{
    const float* xg  = (const float*)d_in[0];   // (1, 2H)
    const float* xm  = (const float*)d_in[1];   // (M, H)
    const float* xj  = (const float*)d_in[2];   // (J, H)
    const int*   mi  = (const int*)  d_in[3];   // (N,)
    const int*   ji  = (const int*)  d_in[4];   // (N,)
    const float* W0  = (const float*)d_in[5];   // (4H, H)
    const float* b0  = (const float*)d_in[6];   // (H,)
    const float* W1  = (const float*)d_in[7];   // (H, H)
    const float* b1  = (const float*)d_in[8];   // (H,)
    const float* W2  = (const float*)d_in[9];   // (H, 1)
    const float* b2  = (const float*)d_in[10];  // (1,)

    int N = in_sizes[3];
    int M = in_sizes[1] / H;
    int J = in_sizes[2] / H;
    float* out = (float*)d_out;

    int nMB = (M + PR - 1) / PR;
    int nJB = (J + PR - 1) / PR;
    int grid_pre = nMB + nJB + 1 + 32;   // rows + G + W1-prep

    precompute_kernel<<<grid_pre, H>>>(xg, xm, xj, W0, b0, W1, M, J, nMB, nJB);
    score_kernel<<<(N + TOPS - 1) / TOPS, 256>>>(mi, ji, b1, W2, b2, N);
    reduce_sum_kernel<<<RB, RT>>>(N);
    finalize_kernel<<<1, RB>>>(out, out_size);
}

// round 9
// speedup vs baseline: 1.6955x; 1.5366x over previous
#include <cuda_runtime.h>
#include <cuda_fp16.h>
#include <math_constants.h>

#define H     128
#define TOPS  128         // ops per score block
#define APAD  136         // halfs per A-smem row (272B, conflict-free frag LDS)
#define PR    16          // rows per precompute block
#define MAXM  1000
#define MAXJ  5000
#define MAXN  200000
#define NBLK  2048        // >= ceil(MAXN/TOPS)

// ---- scratch (device globals; no allocation allowed) ----
__device__ float g_A[MAXM * H];        // x_m  @ W0[256:384]
__device__ float g_B[MAXJ * H];        // x_job@ W0[384:512]
__device__ float g_G[H];               // x_graph @ W0[0:256] + b0
__device__ uint4 g_W1f[4096];          // W1 hi/lo, MMA-fragment-packed
__device__ unsigned long long g_amax;  // packed (ordered(score)<<32) | ~idx
__device__ float g_bm[NBLK];           // per-block max
__device__ float g_bs1[NBLK];          // per-block  sum e^(s-bm)
__device__ float g_bs2[NBLK];          // per-block  sum e^(s-bm)*(s-bm)

static __device__ __forceinline__ unsigned pack_h2(__half a, __half b) {
    __half2 h = __halves2half2(a, b);
    return *reinterpret_cast<unsigned*>(&h);
}

// ============================================================================
// Precompute. Block roles:
//   [0, nMB)       : 16 M-rows each,  W0 slab [2H:3H)
//   [nMB, nMB+nJB) : 16 J-rows each,  W0 slab [3H:4H)
//   nMB+nJB        : G row (2H matvec) + reset argmax
//   +32 blocks     : W1 -> fragment-packed fp16 hi/lo (g_W1f)
// ============================================================================
__global__ __launch_bounds__(H) void precompute_kernel(
    const float* __restrict__ xg, const float* __restrict__ xm,
    const float* __restrict__ xj, const float* __restrict__ W0,
    const float* __restrict__ b0, const float* __restrict__ W1,
    int M, int J, int nMB, int nJB)
{
    __shared__ __align__(16) float xsT[H * 20];
    int b = blockIdx.x, k = threadIdx.x;

    if (b < nMB + nJB) {
        bool isM = (b < nMB);
        int r0 = (isM ? b : b - nMB) * PR;
        int R  = isM ? M : J;
        const float* src = isM ? xm : xj;
        const float* w   = W0 + (isM ? 2 * H * H : 3 * H * H) + k;
        float* dst = isM ? g_A : g_B;
        int rows = R - r0; if (rows > PR) rows = PR;

        #pragma unroll
        for (int r = 0; r < PR; r++) {
            int rr = r0 + ((r < rows) ? r : 0);
            xsT[k * 20 + r] = src[rr * H + k];
        }
        __syncthreads();

        float acc[PR];
        #pragma unroll
        for (int r = 0; r < PR; r++) acc[r] = 0.f;

        #pragma unroll 2
        for (int i = 0; i < H; i++) {
            float wv = __ldg(w + i * H);
            const float4* xp = (const float4*)(xsT + i * 20);
            float4 x0 = xp[0], x1 = xp[1], x2 = xp[2], x3 = xp[3];
            acc[0]  = fmaf(x0.x, wv, acc[0]);  acc[1]  = fmaf(x0.y, wv, acc[1]);
            acc[2]  = fmaf(x0.z, wv, acc[2]);  acc[3]  = fmaf(x0.w, wv, acc[3]);
            acc[4]  = fmaf(x1.x, wv, acc[4]);  acc[5]  = fmaf(x1.y, wv, acc[5]);
            acc[6]  = fmaf(x1.z, wv, acc[6]);  acc[7]  = fmaf(x1.w, wv, acc[7]);
            acc[8]  = fmaf(x2.x, wv, acc[8]);  acc[9]  = fmaf(x2.y, wv, acc[9]);
            acc[10] = fmaf(x2.z, wv, acc[10]); acc[11] = fmaf(x2.w, wv, acc[11]);
            acc[12] = fmaf(x3.x, wv, acc[12]); acc[13] = fmaf(x3.y, wv, acc[13]);
            acc[14] = fmaf(x3.z, wv, acc[14]); acc[15] = fmaf(x3.w, wv, acc[15]);
        }
        for (int r = 0; r < rows; r++) dst[(r0 + r) * H + k] = acc[r];
    } else if (b == nMB + nJB) {
        if (k == 0) g_amax = 0ull;
        xsT[k] = xg[k];
        xsT[H + k] = xg[H + k];
        __syncthreads();
        float acc = b0[k];
        const float* w = W0 + k;
        #pragma unroll 8
        for (int i = 0; i < 2 * H; i++) acc = fmaf(xsT[i], w[i * H], acc);
        g_G[k] = acc;
    } else {
        // W1 fragment packing. 32 blocks x 128 threads = 4096 uint4.
        // w = ((nq*8 + ks)*4 + q)*32 + lane; q: 0=hi nt{0,1},1=hi nt{2,3},
        // 2=lo nt{0,1},3=lo nt{2,3}. Frag b0=(k0,k0+1), b1=(k0+8,k0+9) at
        // col n; uint4 = {b0(nA), b1(nA), b0(nA+8), b1(nA+8)}.
        int w = (b - (nMB + nJB + 1)) * H + k;   // 0..4095
        int lane = w & 31, q = (w >> 5) & 3, ks = (w >> 7) & 7, nq = (w >> 10) & 3;
        int g = lane >> 2, t = lane & 3;
        int k0 = ks * 16 + 2 * t;
        int nA = nq * 32 + (q & 1) * 16 + g;
        int nB = nA + 8;
        bool lo = (q >> 1) != 0;
        float vA0 = __ldg(W1 + k0 * H + nA),       vA1 = __ldg(W1 + (k0 + 1) * H + nA);
        float vA8 = __ldg(W1 + (k0 + 8) * H + nA), vA9 = __ldg(W1 + (k0 + 9) * H + nA);
        float vB0 = __ldg(W1 + k0 * H + nB),       vB1 = __ldg(W1 + (k0 + 1) * H + nB);
        float vB8 = __ldg(W1 + (k0 + 8) * H + nB), vB9 = __ldg(W1 + (k0 + 9) * H + nB);
        #define CVT(v) (lo ? __float2half_rn((v) - __half2float(__float2half_rn(v))) \
                           : __float2half_rn(v))
        uint4 r;
        r.x = pack_h2(CVT(vA0), CVT(vA1));
        r.y = pack_h2(CVT(vA8), CVT(vA9));
        r.z = pack_h2(CVT(vB0), CVT(vB1));
        r.w = pack_h2(CVT(vB8), CVT(vB9));
        #undef CVT
        g_W1f[w] = r;
    }
}

// ============================================================================
// Score kernel: block = 128 ops, 256 threads (8 warps).
// Warp (mg = w>>2, nq = w&3) computes a 64(m) x 32(n) C tile: 4 m-tiles x
// 4 n-tiles of m16n8k16, split-fp16 3-MMA (hh+hl+lh). A hi/lo in dynamic
// smem (row layout, conflict-free frag LDS); B via 4 coalesced LDG.128 per
// ks from fragment-packed g_W1f (L1-hot, 64KB total).
// Epilogue: +b1, relu, *W2, quad shuffles, cross-quarter combine, then
// per-block softmax partials (max/S1/S2) + packed-key atomicMax argmax.
// ============================================================================
__device__ __forceinline__ void mma_f16(float c[4], const unsigned a[4],
                                        unsigned b0, unsigned b1)
{
    asm volatile(
        "mma.sync.aligned.m16n8k16.row.col.f32.f16.f16.f32 "
        "{%0,%1,%2,%3}, {%4,%5,%6,%7}, {%8,%9}, {%0,%1,%2,%3};"
        : "+f"(c[0]), "+f"(c[1]), "+f"(c[2]), "+f"(c[3])
        : "r"(a[0]), "r"(a[1]), "r"(a[2]), "r"(a[3]), "r"(b0), "r"(b1));
}

extern __shared__ __half dsm[];

__global__ __launch_bounds__(256) void score_kernel(
    const int* __restrict__ m_ids, const int* __restrict__ j_ids,
    const float* __restrict__ b1, const float* __restrict__ W2,
    const float* __restrict__ b2p, int N)
{
    __half* Ah = dsm;
    __half* Al = dsm + TOPS * APAD;
    __shared__ int   ids[2 * TOPS];
    __shared__ float b1s[H], w2s[H];
    __shared__ float red[4][TOPS];
    __shared__ float wmax[4], ws1[4], ws2[4];

    int tid = threadIdx.x;
    int base = blockIdx.x * TOPS;
    int cnt = N - base; if (cnt > TOPS) cnt = TOPS;

    if (tid < H) { b1s[tid] = b1[tid]; w2s[tid] = W2[tid]; }
    if (tid < TOPS) ids[tid] = (tid < cnt) ? m_ids[base + tid] : 0;
    else {
        int t = tid - TOPS;
        ids[TOPS + t] = (t < cnt) ? j_ids[base + t] : 0;
    }
    __syncthreads();

    // ---- gen phase: 128 ops x 64 feat-pairs ----
    #pragma unroll 4
    for (int it = 0; it < 32; it++) {
        int idx = it * 256 + tid;
        int op = idx >> 6, fp = idx & 63;
        int m = ids[op], j = ids[TOPS + op];
        float2 gv = *(const float2*)(g_G + fp * 2);
        float2 av = *(const float2*)(g_A + m * H + fp * 2);
        float2 bv = *(const float2*)(g_B + j * H + fp * 2);
        float x0 = fmaxf(gv.x + av.x + bv.x, 0.f);
        float x1 = fmaxf(gv.y + av.y + bv.y, 0.f);
        __half h0 = __float2half_rn(x0), h1 = __float2half_rn(x1);
        __half l0 = __float2half_rn(x0 - __half2float(h0));
        __half l1 = __float2half_rn(x1 - __half2float(h1));
        *(__half2*)(Ah + op * APAD + fp * 2) = __halves2half2(h0, h1);
        *(__half2*)(Al + op * APAD + fp * 2) = __halves2half2(l0, l1);
    }
    __syncthreads();

    // ---- mma phase ----
    int wlin = tid >> 5, lane = tid & 31;
    int mg = wlin >> 2, nq = wlin & 3;
    int g = lane >> 2, t = lane & 3;

    float c[4][4][4];
    #pragma unroll
    for (int mt = 0; mt < 4; mt++)
        #pragma unroll
        for (int nt = 0; nt < 4; nt++)
            { c[mt][nt][0]=0.f; c[mt][nt][1]=0.f; c[mt][nt][2]=0.f; c[mt][nt][3]=0.f; }

    #pragma unroll 1
    for (int ks = 0; ks < 8; ks++) {
        const uint4* bp = g_W1f + ((nq * 8 + ks) * 4) * 32 + lane;
        uint4 bh01 = __ldg(bp);
        uint4 bh23 = __ldg(bp + 32);
        uint4 bl01 = __ldg(bp + 64);
        uint4 bl23 = __ldg(bp + 96);
        int kc = ks * 16 + 2 * t;

        #pragma unroll
        for (int mt = 0; mt < 4; mt++) {
            const __half* Ar = Ah + (mg * 64 + mt * 16 + g) * APAD + kc;
            const __half* Lr = Al + (mg * 64 + mt * 16 + g) * APAD + kc;
            unsigned ah[4], al[4];
            ah[0] = *(const unsigned*)(Ar);
            ah[1] = *(const unsigned*)(Ar + 8 * APAD);
            ah[2] = *(const unsigned*)(Ar + 8);
            ah[3] = *(const unsigned*)(Ar + 8 * APAD + 8);
            al[0] = *(const unsigned*)(Lr);
            al[1] = *(const unsigned*)(Lr + 8 * APAD);
            al[2] = *(const unsigned*)(Lr + 8);
            al[3] = *(const unsigned*)(Lr + 8 * APAD + 8);

            mma_f16(c[mt][0], ah, bh01.x, bh01.y);
            mma_f16(c[mt][0], ah, bl01.x, bl01.y);
            mma_f16(c[mt][0], al, bh01.x, bh01.y);
            mma_f16(c[mt][1], ah, bh01.z, bh01.w);
            mma_f16(c[mt][1], ah, bl01.z, bl01.w);
            mma_f16(c[mt][1], al, bh01.z, bh01.w);
            mma_f16(c[mt][2], ah, bh23.x, bh23.y);
            mma_f16(c[mt][2], ah, bl23.x, bl23.y);
            mma_f16(c[mt][2], al, bh23.x, bh23.y);
            mma_f16(c[mt][3], ah, bh23.z, bh23.w);
            mma_f16(c[mt][3], ah, bl23.z, bl23.w);
            mma_f16(c[mt][3], al, bh23.z, bh23.w);
        }
    }

    // ---- epilogue: relu(+b1) * W2, row sums per n-quarter ----
    #pragma unroll
    for (int mt = 0; mt < 4; mt++) {
        float sl = 0.f, sh = 0.f;
        #pragma unroll
        for (int nt = 0; nt < 4; nt++) {
            int n0 = nq * 32 + nt * 8 + 2 * t;
            float w20 = w2s[n0], w21 = w2s[n0 + 1];
            float bb0 = b1s[n0], bb1 = b1s[n0 + 1];
            sl += fmaxf(c[mt][nt][0] + bb0, 0.f) * w20
                + fmaxf(c[mt][nt][1] + bb1, 0.f) * w21;
            sh += fmaxf(c[mt][nt][2] + bb0, 0.f) * w20
                + fmaxf(c[mt][nt][3] + bb1, 0.f) * w21;
        }
        sl += __shfl_xor_sync(0xffffffffu, sl, 1);
        sl += __shfl_xor_sync(0xffffffffu, sl, 2);
        sh += __shfl_xor_sync(0xffffffffu, sh, 1);
        sh += __shfl_xor_sync(0xffffffffu, sh, 2);
        if (t == 0) {
            int r = mg * 64 + mt * 16 + g;
            red[nq][r]     = sl;
            red[nq][r + 8] = sh;
        }
    }
    __syncthreads();

    // ---- scores + fused argmax + block softmax partials (warps 0-3) ----
    if (tid < TOPS) {
        bool valid = tid < cnt;
        float s = red[0][tid] + red[1][tid] + red[2][tid] + red[3][tid] + b2p[0];

        // deterministic argmax via packed key
        unsigned long long key = 0ull;
        if (valid) {
            unsigned fu = __float_as_uint(s);
            unsigned ord = (fu & 0x80000000u) ? ~fu : (fu | 0x80000000u);
            key = ((unsigned long long)ord << 32) |
                  (unsigned)(~(unsigned)(base + tid));
        }
        #pragma unroll
        for (int off = 16; off >= 1; off >>= 1) {
            unsigned long long o = __shfl_xor_sync(0xffffffffu, key, off);
            if (o > key) key = o;
        }
        if (lane == 0) atomicMax(&g_amax, key);

        // block max (exact, order-free)
        float sv = valid ? s : -CUDART_INF_F;
        float wm = sv;
        #pragma unroll
        for (int off = 16; off >= 1; off >>= 1)
            wm = fmaxf(wm, __shfl_xor_sync(0xffffffffu, wm, off));
        if (lane == 0) wmax[wlin] = wm;
        __syncwarp();
        // need all 4 warps' maxima
        __syncthreads();
        float bm = fmaxf(fmaxf(wmax[0], wmax[1]), fmaxf(wmax[2], wmax[3]));

        float e = 0.f, de = 0.f;
        if (valid) {
            float d = s - bm;
            e = expf(d);
            de = e * d;
        }
        #pragma unroll
        for (int off = 16; off >= 1; off >>= 1) {
            e  += __shfl_xor_sync(0xffffffffu, e, off);
            de += __shfl_xor_sync(0xffffffffu, de, off);
        }
        if (lane == 0) { ws1[wlin] = e; ws2[wlin] = de; }
        __syncthreads();
        if (tid == 0) {
            g_bm[blockIdx.x]  = bm;
            g_bs1[blockIdx.x] = (ws1[0] + ws1[1]) + (ws1[2] + ws1[3]);
            g_bs2[blockIdx.x] = (ws2[0] + ws2[1]) + (ws2[2] + ws2[3]);
        }
    } else {
        __syncthreads();   // match warps 0-3's two barriers
        __syncthreads();
    }
}

// ============================================================================
// Finalize: merge per-block softmax partials (exact rescale), emit outputs.
// ============================================================================
__device__ __forceinline__ float decode_max(unsigned long long key) {
    unsigned ord = (unsigned)(key >> 32);
    unsigned fu = (ord & 0x80000000u) ? (ord ^ 0x80000000u) : ~ord;
    return __uint_as_float(fu);
}

__global__ __launch_bounds__(256) void finalize_kernel(
    float* __restrict__ out, int out_size, int nB)
{
    __shared__ float s1s[256], s2s[256];
    int tid = threadIdx.x;
    float Mx = decode_max(g_amax);
    float s1 = 0.f, s2 = 0.f;
    for (int b = tid; b < nB; b += 256) {
        float lm = g_bm[b];
        float d  = lm - Mx;
        float w  = expf(d);
        float p1 = g_bs1[b];
        s1 += p1 * w;
        s2 += (g_bs2[b] + d * p1) * w;
    }
    s1s[tid] = s1; s2s[tid] = s2;
    __syncthreads();
    for (int off = 128; off; off >>= 1) {
        if (tid < off) { s1s[tid] += s1s[tid + off]; s2s[tid] += s2s[tid + off]; }
        __syncthreads();
    }
    if (tid == 0) {
        unsigned long long key = g_amax;
        int idx = (int)(~(unsigned)key);
        float S1 = s1s[0], S2 = s2s[0];
        float lz = logf(S1);
        float vals[4];
        vals[0] = (float)idx;
        vals[1] = 1.f / S1;      // probs[idx]  (argmax => shifted score 0)
        vals[2] = -lz;           // logp[idx]
        vals[3] = lz - S2 / S1;  // entropy
        int nw = out_size < 4 ? out_size : 4;
        for (int i = 0; i < nw; i++) out[i] = vals[i];
    }
}

// ============================================================================
extern "C" void kernel_launch(void* const* d_in, const int* in_sizes, int n_in,
                              void* d_out, int out_size)
{
    const float* xg  = (const float*)d_in[0];   // (1, 2H)
    const float* xm  = (const float*)d_in[1];   // (M, H)
    const float* xj  = (const float*)d_in[2];   // (J, H)
    const int*   mi  = (const int*)  d_in[3];   // (N,)
    const int*   ji  = (const int*)  d_in[4];   // (N,)
    const float* W0  = (const float*)d_in[5];   // (4H, H)
    const float* b0  = (const float*)d_in[6];   // (H,)
    const float* W1  = (const float*)d_in[7];   // (H, H)
    const float* b1  = (const float*)d_in[8];   // (H,)
    const float* W2  = (const float*)d_in[9];   // (H, 1)
    const float* b2  = (const float*)d_in[10];  // (1,)

    int N = in_sizes[3];
    int M = in_sizes[1] / H;
    int J = in_sizes[2] / H;
    float* out = (float*)d_out;

    int nMB = (M + PR - 1) / PR;
    int nJB = (J + PR - 1) / PR;
    int grid_pre = nMB + nJB + 1 + 32;
    int nB = (N + TOPS - 1) / TOPS;
    int smem = 2 * TOPS * APAD * (int)sizeof(__half);   // 69632 B

    static int attr_set = 0;
    if (!attr_set) {
        cudaFuncSetAttribute(score_kernel,
                             cudaFuncAttributeMaxDynamicSharedMemorySize, smem);
        attr_set = 1;
    }

    precompute_kernel<<<grid_pre, H>>>(xg, xm, xj, W0, b0, W1, M, J, nMB, nJB);
    score_kernel<<<nB, 256, smem>>>(mi, ji, b1, W2, b2, N);
    finalize_kernel<<<1, 256>>>(out, out_size, nB);
}

// round 12
// speedup vs baseline: 2.8683x; 1.6916x over previous
#include <cuda_runtime.h>
#include <cuda_fp16.h>
#include <math_constants.h>

#define H     128
#define TOPS  128         // ops per score block
#define APAD  136         // halfs per A-smem row (272B, conflict-free frag LDS)
#define PR    8           // rows per precompute block
#define MAXM  1000
#define MAXJ  5000
#define MAXN  200000
#define NBLK  2048        // >= ceil(MAXN/TOPS)

// ---- scratch (device globals; no allocation allowed) ----
__device__ float g_A[MAXM * H];        // x_m  @ W0[256:384]
__device__ float g_B[MAXJ * H];        // x_job@ W0[384:512]
__device__ float g_G[H];               // x_graph @ W0[0:256] + b0
__device__ uint4 g_W1f[4096];          // W1 hi/lo, MMA-fragment-packed
__device__ unsigned long long g_amax;  // packed (ordered(score)<<32) | ~idx
__device__ float g_bm[NBLK];           // per-block max
__device__ float g_bs1[NBLK];          // per-block  sum e^(s-bm)
__device__ float g_bs2[NBLK];          // per-block  sum e^(s-bm)*(s-bm)

static __device__ __forceinline__ unsigned pack_h2(__half a, __half b) {
    __half2 h = __halves2half2(a, b);
    return *reinterpret_cast<unsigned*>(&h);
}

// ============================================================================
// Precompute. Block roles:
//   [0, nMB)       : 8 M-rows each,  W0 slab [2H:3H)
//   [nMB, nMB+nJB) : 8 J-rows each,  W0 slab [3H:4H)
//   nMB+nJB        : G row (2H matvec) + reset argmax
//   +32 blocks     : W1 -> fragment-packed fp16 hi/lo (g_W1f)
// PR=8 doubles the grid (~20 warps/SM) for this latency-bound matvec.
// ============================================================================
__global__ __launch_bounds__(H) void precompute_kernel(
    const float* __restrict__ xg, const float* __restrict__ xm,
    const float* __restrict__ xj, const float* __restrict__ W0,
    const float* __restrict__ b0, const float* __restrict__ W1,
    int M, int J, int nMB, int nJB)
{
    __shared__ __align__(16) float xsT[H * 12];
    int b = blockIdx.x, k = threadIdx.x;

    if (b < nMB + nJB) {
        bool isM = (b < nMB);
        int r0 = (isM ? b : b - nMB) * PR;
        int R  = isM ? M : J;
        const float* src = isM ? xm : xj;
        const float* w   = W0 + (isM ? 2 * H * H : 3 * H * H) + k;
        float* dst = isM ? g_A : g_B;
        int rows = R - r0; if (rows > PR) rows = PR;

        #pragma unroll
        for (int r = 0; r < PR; r++) {
            int rr = r0 + ((r < rows) ? r : 0);
            xsT[k * 12 + r] = src[rr * H + k];
        }
        __syncthreads();

        float acc[PR];
        #pragma unroll
        for (int r = 0; r < PR; r++) acc[r] = 0.f;

        #pragma unroll 4
        for (int i = 0; i < H; i++) {
            float wv = __ldg(w + i * H);
            const float4* xp = (const float4*)(xsT + i * 12);
            float4 x0 = xp[0], x1 = xp[1];
            acc[0] = fmaf(x0.x, wv, acc[0]);  acc[1] = fmaf(x0.y, wv, acc[1]);
            acc[2] = fmaf(x0.z, wv, acc[2]);  acc[3] = fmaf(x0.w, wv, acc[3]);
            acc[4] = fmaf(x1.x, wv, acc[4]);  acc[5] = fmaf(x1.y, wv, acc[5]);
            acc[6] = fmaf(x1.z, wv, acc[6]);  acc[7] = fmaf(x1.w, wv, acc[7]);
        }
        for (int r = 0; r < rows; r++) dst[(r0 + r) * H + k] = acc[r];
    } else if (b == nMB + nJB) {
        if (k == 0) g_amax = 0ull;
        xsT[k] = xg[k];
        xsT[H + k] = xg[H + k];
        __syncthreads();
        float acc = b0[k];
        const float* w = W0 + k;
        #pragma unroll 8
        for (int i = 0; i < 2 * H; i++) acc = fmaf(xsT[i], w[i * H], acc);
        g_G[k] = acc;
    } else {
        // W1 fragment packing. 32 blocks x 128 threads = 4096 uint4.
        // w = ((nq*8 + ks)*4 + q)*32 + lane; q: 0=hi nt{0,1},1=hi nt{2,3},
        // 2=lo nt{0,1},3=lo nt{2,3}. Frag b0=(k0,k0+1), b1=(k0+8,k0+9) at
        // col n; uint4 = {b0(nA), b1(nA), b0(nA+8), b1(nA+8)}.
        int w = (b - (nMB + nJB + 1)) * H + k;   // 0..4095
        int lane = w & 31, q = (w >> 5) & 3, ks = (w >> 7) & 7, nq = (w >> 10) & 3;
        int g = lane >> 2, t = lane & 3;
        int k0 = ks * 16 + 2 * t;
        int nA = nq * 32 + (q & 1) * 16 + g;
        int nB = nA + 8;
        bool lo = (q >> 1) != 0;
        float vA0 = __ldg(W1 + k0 * H + nA),       vA1 = __ldg(W1 + (k0 + 1) * H + nA);
        float vA8 = __ldg(W1 + (k0 + 8) * H + nA), vA9 = __ldg(W1 + (k0 + 9) * H + nA);
        float vB0 = __ldg(W1 + k0 * H + nB),       vB1 = __ldg(W1 + (k0 + 1) * H + nB);
        float vB8 = __ldg(W1 + (k0 + 8) * H + nB), vB9 = __ldg(W1 + (k0 + 9) * H + nB);
        #define CVT(v) (lo ? __float2half_rn((v) - __half2float(__float2half_rn(v))) \
                           : __float2half_rn(v))
        uint4 r;
        r.x = pack_h2(CVT(vA0), CVT(vA1));
        r.y = pack_h2(CVT(vA8), CVT(vA9));
        r.z = pack_h2(CVT(vB0), CVT(vB1));
        r.w = pack_h2(CVT(vB8), CVT(vB9));
        #undef CVT
        g_W1f[w] = r;
    }
}

// ============================================================================
// Score kernel: block = 128 ops, 256 threads (8 warps).
// Warp (mg = w>>2, nq = w&3) computes a 64(m) x 32(n) C tile: 4 m-tiles x
// 4 n-tiles of m16n8k16. Precision scheme: A (=relu H0) rounded once to
// fp16; W1 kept exact as fp16 hi+lo -> 2 MMAs per tile (ah*bh + ah*bl).
// Remaining error is only A's fp16 rounding (~5e-5 on scores, spread ~0.12).
// A in static smem (row layout, conflict-free frag LDS); B via 4 coalesced
// LDG.128 per ks from fragment-packed g_W1f (L1-hot, 64KB total).
// Epilogue: +b1, relu, *W2, quad shuffles, cross-quarter combine, then
// per-block softmax partials (max/S1/S2) + packed-key atomicMax argmax.
// ============================================================================
__device__ __forceinline__ void mma_f16(float c[4], const unsigned a[4],
                                        unsigned b0, unsigned b1)
{
    asm volatile(
        "mma.sync.aligned.m16n8k16.row.col.f32.f16.f16.f32 "
        "{%0,%1,%2,%3}, {%4,%5,%6,%7}, {%8,%9}, {%0,%1,%2,%3};"
        : "+f"(c[0]), "+f"(c[1]), "+f"(c[2]), "+f"(c[3])
        : "r"(a[0]), "r"(a[1]), "r"(a[2]), "r"(a[3]), "r"(b0), "r"(b1));
}

__global__ __launch_bounds__(256) void score_kernel(
    const int* __restrict__ m_ids, const int* __restrict__ j_ids,
    const float* __restrict__ b1, const float* __restrict__ W2,
    const float* __restrict__ b2p, int N)
{
    __shared__ __align__(16) __half Ah[TOPS * APAD];   // 34.8KB
    __shared__ int   ids[2 * TOPS];
    __shared__ float b1s[H], w2s[H];
    __shared__ float red[4][TOPS];
    __shared__ float wmax[4], ws1[4], ws2[4];

    int tid = threadIdx.x;
    int base = blockIdx.x * TOPS;
    int cnt = N - base; if (cnt > TOPS) cnt = TOPS;

    if (tid < H) { b1s[tid] = b1[tid]; w2s[tid] = W2[tid]; }
    if (tid < TOPS) ids[tid] = (tid < cnt) ? m_ids[base + tid] : 0;
    else {
        int t = tid - TOPS;
        ids[TOPS + t] = (t < cnt) ? j_ids[base + t] : 0;
    }
    __syncthreads();

    // ---- gen phase: 128 ops x 64 feat-pairs, coalesced float2 gathers ----
    #pragma unroll 4
    for (int it = 0; it < 32; it++) {
        int idx = it * 256 + tid;
        int op = idx >> 6, fp = idx & 63;
        int m = ids[op], j = ids[TOPS + op];
        float2 gv = *(const float2*)(g_G + fp * 2);
        float2 av = *(const float2*)(g_A + m * H + fp * 2);
        float2 bv = *(const float2*)(g_B + j * H + fp * 2);
        float x0 = fmaxf(gv.x + av.x + bv.x, 0.f);
        float x1 = fmaxf(gv.y + av.y + bv.y, 0.f);
        *(__half2*)(Ah + op * APAD + fp * 2) =
            __halves2half2(__float2half_rn(x0), __float2half_rn(x1));
    }
    __syncthreads();

    // ---- mma phase ----
    int wlin = tid >> 5, lane = tid & 31;
    int mg = wlin >> 2, nq = wlin & 3;
    int g = lane >> 2, t = lane & 3;

    float c[4][4][4];
    #pragma unroll
    for (int mt = 0; mt < 4; mt++)
        #pragma unroll
        for (int nt = 0; nt < 4; nt++)
            { c[mt][nt][0]=0.f; c[mt][nt][1]=0.f; c[mt][nt][2]=0.f; c[mt][nt][3]=0.f; }

    #pragma unroll 1
    for (int ks = 0; ks < 8; ks++) {
        const uint4* bp = g_W1f + ((nq * 8 + ks) * 4) * 32 + lane;
        uint4 bh01 = __ldg(bp);
        uint4 bh23 = __ldg(bp + 32);
        uint4 bl01 = __ldg(bp + 64);
        uint4 bl23 = __ldg(bp + 96);
        int kc = ks * 16 + 2 * t;

        #pragma unroll
        for (int mt = 0; mt < 4; mt++) {
            const __half* Ar = Ah + (mg * 64 + mt * 16 + g) * APAD + kc;
            unsigned ah[4];
            ah[0] = *(const unsigned*)(Ar);
            ah[1] = *(const unsigned*)(Ar + 8 * APAD);
            ah[2] = *(const unsigned*)(Ar + 8);
            ah[3] = *(const unsigned*)(Ar + 8 * APAD + 8);

            mma_f16(c[mt][0], ah, bh01.x, bh01.y);
            mma_f16(c[mt][0], ah, bl01.x, bl01.y);
            mma_f16(c[mt][1], ah, bh01.z, bh01.w);
            mma_f16(c[mt][1], ah, bl01.z, bl01.w);
            mma_f16(c[mt][2], ah, bh23.x, bh23.y);
            mma_f16(c[mt][2], ah, bl23.x, bl23.y);
            mma_f16(c[mt][3], ah, bh23.z, bh23.w);
            mma_f16(c[mt][3], ah, bl23.z, bl23.w);
        }
    }

    // ---- epilogue: relu(+b1) * W2, row sums per n-quarter ----
    #pragma unroll
    for (int mt = 0; mt < 4; mt++) {
        float sl = 0.f, sh = 0.f;
        #pragma unroll
        for (int nt = 0; nt < 4; nt++) {
            int n0 = nq * 32 + nt * 8 + 2 * t;
            float w20 = w2s[n0], w21 = w2s[n0 + 1];
            float bb0 = b1s[n0], bb1 = b1s[n0 + 1];
            sl += fmaxf(c[mt][nt][0] + bb0, 0.f) * w20
                + fmaxf(c[mt][nt][1] + bb1, 0.f) * w21;
            sh += fmaxf(c[mt][nt][2] + bb0, 0.f) * w20
                + fmaxf(c[mt][nt][3] + bb1, 0.f) * w21;
        }
        sl += __shfl_xor_sync(0xffffffffu, sl, 1);
        sl += __shfl_xor_sync(0xffffffffu, sl, 2);
        sh += __shfl_xor_sync(0xffffffffu, sh, 1);
        sh += __shfl_xor_sync(0xffffffffu, sh, 2);
        if (t == 0) {
            int r = mg * 64 + mt * 16 + g;
            red[nq][r]     = sl;
            red[nq][r + 8] = sh;
        }
    }
    __syncthreads();

    // ---- scores + fused argmax + block softmax partials (warps 0-3) ----
    if (tid < TOPS) {
        bool valid = tid < cnt;
        float s = red[0][tid] + red[1][tid] + red[2][tid] + red[3][tid] + b2p[0];

        // deterministic argmax via packed key
        unsigned long long key = 0ull;
        if (valid) {
            unsigned fu = __float_as_uint(s);
            unsigned ord = (fu & 0x80000000u) ? ~fu : (fu | 0x80000000u);
            key = ((unsigned long long)ord << 32) |
                  (unsigned)(~(unsigned)(base + tid));
        }
        #pragma unroll
        for (int off = 16; off >= 1; off >>= 1) {
            unsigned long long o = __shfl_xor_sync(0xffffffffu, key, off);
            if (o > key) key = o;
        }
        if (lane == 0) atomicMax(&g_amax, key);

        // block max (exact, order-free)
        float sv = valid ? s : -CUDART_INF_F;
        float wm = sv;
        #pragma unroll
        for (int off = 16; off >= 1; off >>= 1)
            wm = fmaxf(wm, __shfl_xor_sync(0xffffffffu, wm, off));
        if (lane == 0) wmax[wlin] = wm;
        __syncwarp();
        __syncthreads();
        float bm = fmaxf(fmaxf(wmax[0], wmax[1]), fmaxf(wmax[2], wmax[3]));

        float e = 0.f, de = 0.f;
        if (valid) {
            float d = s - bm;
            e = expf(d);
            de = e * d;
        }
        #pragma unroll
        for (int off = 16; off >= 1; off >>= 1) {
            e  += __shfl_xor_sync(0xffffffffu, e, off);
            de += __shfl_xor_sync(0xffffffffu, de, off);
        }
        if (lane == 0) { ws1[wlin] = e; ws2[wlin] = de; }
        __syncthreads();
        if (tid == 0) {
            g_bm[blockIdx.x]  = bm;
            g_bs1[blockIdx.x] = (ws1[0] + ws1[1]) + (ws1[2] + ws1[3]);
            g_bs2[blockIdx.x] = (ws2[0] + ws2[1]) + (ws2[2] + ws2[3]);
        }
    } else {
        __syncthreads();   // match warps 0-3's two barriers
        __syncthreads();
    }
}

// ============================================================================
// Finalize: merge per-block softmax partials (exact rescale), emit outputs.
// ============================================================================
__device__ __forceinline__ float decode_max(unsigned long long key) {
    unsigned ord = (unsigned)(key >> 32);
    unsigned fu = (ord & 0x80000000u) ? (ord ^ 0x80000000u) : ~ord;
    return __uint_as_float(fu);
}

__global__ __launch_bounds__(256) void finalize_kernel(
    float* __restrict__ out, int out_size, int nB)
{
    __shared__ float s1s[256], s2s[256];
    int tid = threadIdx.x;
    float Mx = decode_max(g_amax);
    float s1 = 0.f, s2 = 0.f;
    for (int b = tid; b < nB; b += 256) {
        float lm = g_bm[b];
        float d  = lm - Mx;
        float w  = expf(d);
        float p1 = g_bs1[b];
        s1 += p1 * w;
        s2 += (g_bs2[b] + d * p1) * w;
    }
    s1s[tid] = s1; s2s[tid] = s2;
    __syncthreads();
    for (int off = 128; off; off >>= 1) {
        if (tid < off) { s1s[tid] += s1s[tid + off]; s2s[tid] += s2s[tid + off]; }
        __syncthreads();
    }
    if (tid == 0) {
        unsigned long long key = g_amax;
        int idx = (int)(~(unsigned)key);
        float S1 = s1s[0], S2 = s2s[0];
        float lz = logf(S1);
        float vals[4];
        vals[0] = (float)idx;
        vals[1] = 1.f / S1;      // probs[idx]  (argmax => shifted score 0)
        vals[2] = -lz;           // logp[idx]
        vals[3] = lz - S2 / S1;  // entropy
        int nw = out_size < 4 ? out_size : 4;
        for (int i = 0; i < nw; i++) out[i] = vals[i];
    }
}

// ============================================================================
extern "C" void kernel_launch(void* const* d_in, const int* in_sizes, int n_in,
                              void* d_out, int out_size)
{
    const float* xg  = (const float*)d_in[0];   // (1, 2H)
    const float* xm  = (const float*)d_in[1];   // (M, H)
    const float* xj  = (const float*)d_in[2];   // (J, H)
    const int*   mi  = (const int*)  d_in[3];   // (N,)
    const int*   ji  = (const int*)  d_in[4];   // (N,)
    const float* W0  = (const float*)d_in[5];   // (4H, H)
    const float* b0  = (const float*)d_in[6];   // (H,)
    const float* W1  = (const float*)d_in[7];   // (H, H)
    const float* b1  = (const float*)d_in[8];   // (H,)
    const float* W2  = (const float*)d_in[9];   // (H, 1)
    const float* b2  = (const float*)d_in[10];  // (1,)

    int N = in_sizes[3];
    int M = in_sizes[1] / H;
    int J = in_sizes[2] / H;
    float* out = (float*)d_out;

    int nMB = (M + PR - 1) / PR;
    int nJB = (J + PR - 1) / PR;
    int grid_pre = nMB + nJB + 1 + 32;
    int nB = (N + TOPS - 1) / TOPS;

    precompute_kernel<<<grid_pre, H>>>(xg, xm, xj, W0, b0, W1, M, J, nMB, nJB);
    score_kernel<<<nB, 256>>>(mi, ji, b1, W2, b2, N);
    finalize_kernel<<<1, 256>>>(out, out_size, nB);
}